// round 3
// baseline (speedup 1.0000x reference)
#include <cuda_runtime.h>
#include <cuda_bf16.h>

#define N_NODES 50000
#define D_FEAT  128
#define FULL 0xffffffffu

// CSR row offsets into the sorted edge list. 50001 ints.
__device__ int g_offsets[N_NODES + 1];

// Kernel A: boundary-diff scatter. edge_src is sorted; thread e fills
// offsets[n] = e for all n in (edge_src[e-1], edge_src[e]].
__global__ void build_offsets_kernel(const int* __restrict__ edge_src, int n_edges) {
    int e = blockIdx.x * blockDim.x + threadIdx.x;
    if (e >= n_edges) return;
    int s1 = edge_src[e];
    int s0 = (e == 0) ? -1 : edge_src[e - 1];
    for (int n = s0 + 1; n <= s1; n++) g_offsets[n] = e;
    if (e == n_edges - 1) {
        for (int n = s1 + 1; n <= N_NODES; n++) g_offsets[n] = n_edges;
    }
}

// Kernel B: one warp per node. Lane-parallel index load (one coalesced load
// covers 32 edges), shuffle-broadcast indices, 8 gathers in flight.
__global__ void __launch_bounds__(256)
graph_pool_kernel(const float4* __restrict__ x,
                  const int* __restrict__ edge_dst,
                  float4* __restrict__ out) {
    int warp_id = (blockIdx.x * blockDim.x + threadIdx.x) >> 5;
    int lane = threadIdx.x & 31;
    if (warp_id >= N_NODES) return;

    int beg = g_offsets[warp_id];
    int end = g_offsets[warp_id + 1];

    float4 acc0 = x[warp_id * 32 + lane];   // self feature
    float4 acc1 = make_float4(0.f, 0.f, 0.f, 0.f);

    for (int base = beg; base < end; base += 32) {
        // one coalesced load of up to 32 edge indices
        int ep = base + lane;
        int idx = (ep < end) ? edge_dst[ep] : 0;
        int m = min(end - base, 32);

        int k = 0;
        for (; k + 8 <= m; k += 8) {
            int d0 = __shfl_sync(FULL, idx, k + 0);
            int d1 = __shfl_sync(FULL, idx, k + 1);
            int d2 = __shfl_sync(FULL, idx, k + 2);
            int d3 = __shfl_sync(FULL, idx, k + 3);
            int d4 = __shfl_sync(FULL, idx, k + 4);
            int d5 = __shfl_sync(FULL, idx, k + 5);
            int d6 = __shfl_sync(FULL, idx, k + 6);
            int d7 = __shfl_sync(FULL, idx, k + 7);
            float4 v0 = __ldg(&x[d0 * 32 + lane]);
            float4 v1 = __ldg(&x[d1 * 32 + lane]);
            float4 v2 = __ldg(&x[d2 * 32 + lane]);
            float4 v3 = __ldg(&x[d3 * 32 + lane]);
            float4 v4 = __ldg(&x[d4 * 32 + lane]);
            float4 v5 = __ldg(&x[d5 * 32 + lane]);
            float4 v6 = __ldg(&x[d6 * 32 + lane]);
            float4 v7 = __ldg(&x[d7 * 32 + lane]);
            acc0.x += v0.x; acc0.y += v0.y; acc0.z += v0.z; acc0.w += v0.w;
            acc1.x += v1.x; acc1.y += v1.y; acc1.z += v1.z; acc1.w += v1.w;
            acc0.x += v2.x; acc0.y += v2.y; acc0.z += v2.z; acc0.w += v2.w;
            acc1.x += v3.x; acc1.y += v3.y; acc1.z += v3.z; acc1.w += v3.w;
            acc0.x += v4.x; acc0.y += v4.y; acc0.z += v4.z; acc0.w += v4.w;
            acc1.x += v5.x; acc1.y += v5.y; acc1.z += v5.z; acc1.w += v5.w;
            acc0.x += v6.x; acc0.y += v6.y; acc0.z += v6.z; acc0.w += v6.w;
            acc1.x += v7.x; acc1.y += v7.y; acc1.z += v7.z; acc1.w += v7.w;
        }
        for (; k + 4 <= m; k += 4) {
            int d0 = __shfl_sync(FULL, idx, k + 0);
            int d1 = __shfl_sync(FULL, idx, k + 1);
            int d2 = __shfl_sync(FULL, idx, k + 2);
            int d3 = __shfl_sync(FULL, idx, k + 3);
            float4 v0 = __ldg(&x[d0 * 32 + lane]);
            float4 v1 = __ldg(&x[d1 * 32 + lane]);
            float4 v2 = __ldg(&x[d2 * 32 + lane]);
            float4 v3 = __ldg(&x[d3 * 32 + lane]);
            acc0.x += v0.x; acc0.y += v0.y; acc0.z += v0.z; acc0.w += v0.w;
            acc1.x += v1.x; acc1.y += v1.y; acc1.z += v1.z; acc1.w += v1.w;
            acc0.x += v2.x; acc0.y += v2.y; acc0.z += v2.z; acc0.w += v2.w;
            acc1.x += v3.x; acc1.y += v3.y; acc1.z += v3.z; acc1.w += v3.w;
        }
        for (; k < m; k++) {
            int d = __shfl_sync(FULL, idx, k);
            float4 v = __ldg(&x[d * 32 + lane]);
            acc0.x += v.x; acc0.y += v.y; acc0.z += v.z; acc0.w += v.w;
        }
    }

    acc0.x += acc1.x; acc0.y += acc1.y; acc0.z += acc1.z; acc0.w += acc1.w;
    out[warp_id * 32 + lane] = acc0;
}

extern "C" void kernel_launch(void* const* d_in, const int* in_sizes, int n_in,
                              void* d_out, int out_size) {
    const float* x = (const float*)d_in[0];
    const int* edge_src = (const int*)d_in[1];
    const int* edge_dst = (const int*)d_in[2];
    float* out = (float*)d_out;
    int n_edges = in_sizes[1];

    // Kernel A: O(E) boundary-diff offsets
    {
        int threads = 256;
        int blocks = (n_edges + threads - 1) / threads;
        build_offsets_kernel<<<blocks, threads>>>(edge_src, n_edges);
    }

    // Kernel B: one warp per node, 8 warps per block
    {
        int threads = 256;
        int warps_per_block = threads / 32;
        int blocks = (N_NODES + warps_per_block - 1) / warps_per_block;
        graph_pool_kernel<<<blocks, threads>>>((const float4*)x, edge_dst,
                                               (float4*)out);
    }
}

// round 4
// speedup vs baseline: 1.0606x; 1.0606x over previous
#include <cuda_runtime.h>
#include <cuda_bf16.h>

#define N_NODES 50000
#define D_FEAT  128

// CSR row offsets into the sorted edge list. 50001 ints.
__device__ int g_offsets[N_NODES + 1];

// Kernel A: boundary-diff scatter. edge_src is sorted; thread e fills
// offsets[n] = e for all n in (edge_src[e-1], edge_src[e]].
__global__ void build_offsets_kernel(const int* __restrict__ edge_src, int n_edges) {
    int e = blockIdx.x * blockDim.x + threadIdx.x;
    if (e >= n_edges) return;
    int s1 = edge_src[e];
    int s0 = (e == 0) ? -1 : edge_src[e - 1];
    for (int n = s0 + 1; n <= s1; n++) g_offsets[n] = e;
    if (e == n_edges - 1) {
        for (int n = s1 + 1; n <= N_NODES; n++) g_offsets[n] = n_edges;
    }
}

// Kernel B: one warp per node. Straight-line broadcast index loads (L1-hot,
// edge_dst is streamed sequentially) feeding 8 independent row gathers in
// flight, two accumulator chains.
__global__ void __launch_bounds__(256)
graph_pool_kernel(const float4* __restrict__ x,
                  const int* __restrict__ edge_dst,
                  float4* __restrict__ out) {
    int warp_id = (blockIdx.x * blockDim.x + threadIdx.x) >> 5;
    int lane = threadIdx.x & 31;
    if (warp_id >= N_NODES) return;

    int beg = g_offsets[warp_id];
    int end = g_offsets[warp_id + 1];

    float4 acc0 = x[warp_id * 32 + lane];   // self feature
    float4 acc1 = make_float4(0.f, 0.f, 0.f, 0.f);

    int e = beg;
    // 8 independent gathers in flight
    for (; e + 8 <= end; e += 8) {
        int d0 = edge_dst[e + 0];
        int d1 = edge_dst[e + 1];
        int d2 = edge_dst[e + 2];
        int d3 = edge_dst[e + 3];
        int d4 = edge_dst[e + 4];
        int d5 = edge_dst[e + 5];
        int d6 = edge_dst[e + 6];
        int d7 = edge_dst[e + 7];
        float4 v0 = __ldg(&x[d0 * 32 + lane]);
        float4 v1 = __ldg(&x[d1 * 32 + lane]);
        float4 v2 = __ldg(&x[d2 * 32 + lane]);
        float4 v3 = __ldg(&x[d3 * 32 + lane]);
        float4 v4 = __ldg(&x[d4 * 32 + lane]);
        float4 v5 = __ldg(&x[d5 * 32 + lane]);
        float4 v6 = __ldg(&x[d6 * 32 + lane]);
        float4 v7 = __ldg(&x[d7 * 32 + lane]);
        acc0.x += v0.x; acc0.y += v0.y; acc0.z += v0.z; acc0.w += v0.w;
        acc1.x += v1.x; acc1.y += v1.y; acc1.z += v1.z; acc1.w += v1.w;
        acc0.x += v2.x; acc0.y += v2.y; acc0.z += v2.z; acc0.w += v2.w;
        acc1.x += v3.x; acc1.y += v3.y; acc1.z += v3.z; acc1.w += v3.w;
        acc0.x += v4.x; acc0.y += v4.y; acc0.z += v4.z; acc0.w += v4.w;
        acc1.x += v5.x; acc1.y += v5.y; acc1.z += v5.z; acc1.w += v5.w;
        acc0.x += v6.x; acc0.y += v6.y; acc0.z += v6.z; acc0.w += v6.w;
        acc1.x += v7.x; acc1.y += v7.y; acc1.z += v7.z; acc1.w += v7.w;
    }
    for (; e + 4 <= end; e += 4) {
        int d0 = edge_dst[e + 0];
        int d1 = edge_dst[e + 1];
        int d2 = edge_dst[e + 2];
        int d3 = edge_dst[e + 3];
        float4 v0 = __ldg(&x[d0 * 32 + lane]);
        float4 v1 = __ldg(&x[d1 * 32 + lane]);
        float4 v2 = __ldg(&x[d2 * 32 + lane]);
        float4 v3 = __ldg(&x[d3 * 32 + lane]);
        acc0.x += v0.x; acc0.y += v0.y; acc0.z += v0.z; acc0.w += v0.w;
        acc1.x += v1.x; acc1.y += v1.y; acc1.z += v1.z; acc1.w += v1.w;
        acc0.x += v2.x; acc0.y += v2.y; acc0.z += v2.z; acc0.w += v2.w;
        acc1.x += v3.x; acc1.y += v3.y; acc1.z += v3.z; acc1.w += v3.w;
    }
    for (; e < end; e++) {
        int d = edge_dst[e];
        float4 v = __ldg(&x[d * 32 + lane]);
        acc0.x += v.x; acc0.y += v.y; acc0.z += v.z; acc0.w += v.w;
    }

    acc0.x += acc1.x; acc0.y += acc1.y; acc0.z += acc1.z; acc0.w += acc1.w;
    out[warp_id * 32 + lane] = acc0;
}

extern "C" void kernel_launch(void* const* d_in, const int* in_sizes, int n_in,
                              void* d_out, int out_size) {
    const float* x = (const float*)d_in[0];
    const int* edge_src = (const int*)d_in[1];
    const int* edge_dst = (const int*)d_in[2];
    float* out = (float*)d_out;
    int n_edges = in_sizes[1];

    // Kernel A: O(E) boundary-diff offsets
    {
        int threads = 256;
        int blocks = (n_edges + threads - 1) / threads;
        build_offsets_kernel<<<blocks, threads>>>(edge_src, n_edges);
    }

    // Kernel B: one warp per node, 8 warps per block
    {
        int threads = 256;
        int warps_per_block = threads / 32;
        int blocks = (N_NODES + warps_per_block - 1) / warps_per_block;
        graph_pool_kernel<<<blocks, threads>>>((const float4*)x, edge_dst,
                                               (float4*)out);
    }
}